// round 4
// baseline (speedup 1.0000x reference)
#include <cuda_runtime.h>
#include <cuda_bf16.h>
#include <cstdint>

// CRF forward scan, exp domain. 128 persistent CTAs, counter handoff.
// E = exp(transitions) f32 in registers (2 rows x 64 strided cols / thread,
// packed f32x2). W published as f32. Row reduction = warp shuffle only.
// Normalizer (lagged, sqrt-damped) computed entirely OFF the critical path.

#define T 2048
#define ROWS 16
#define NBLK 128
#define NTHR 256
#define START_IDX 0
#define END_IDX 1

__device__ __align__(16) float g_Ef[(size_t)T * T];   // 16 MB exp(transitions)
__device__ __align__(16) float g_Wf[2][T];            // f32 W, double buffered
__device__ unsigned g_cnt;                            // monotonic step counter

typedef unsigned long long ull;

__device__ __forceinline__ ull pack2f(float a, float b) {
    ull r; asm("mov.b64 %0, {%1, %2};" : "=l"(r) : "f"(a), "f"(b)); return r;
}
__device__ __forceinline__ void unpack2f(ull p, float& a, float& b) {
    asm("mov.b64 {%0, %1}, %2;" : "=f"(a), "=f"(b) : "l"(p));
}
#define FMA2(acc, a, b) \
    asm("fma.rn.f32x2 %0, %1, %2, %0;" : "+l"(acc) : "l"(a), "l"(b))

__device__ __forceinline__ unsigned poll_once() {
    unsigned c;
    asm volatile("ld.relaxed.gpu.global.u32 %0, [%1];" : "=r"(c) : "l"(&g_cnt));
    return c;
}

__global__ void crf_init(const float* __restrict__ trans) {
    size_t idx = (size_t)blockIdx.x * blockDim.x + threadIdx.x;
    size_t stride = (size_t)gridDim.x * blockDim.x;
    for (size_t i = idx; i < (size_t)T * T; i += stride)
        g_Ef[i] = __expf(trans[i]);
    if (idx < T) {
        g_Wf[0][idx] = (idx == START_IDX) ? 1.0f : 0.0f;
        g_Wf[1][idx] = 0.0f;
    }
    if (idx == 0) g_cnt = 0u;
}

__global__ void __launch_bounds__(NTHR, 1)
crf_main(const float* __restrict__ h, const float* __restrict__ trans,
         float* __restrict__ out, int S) {
    __shared__ __align__(16) float sW[T];      // 8KB staged W (f32)
    __shared__ __align__(16) float sOut[ROWS];

    const int tid = threadIdx.x;
    const int wid = tid >> 5;
    const int ln = tid & 31;
    const int b = blockIdx.x;
    const int r0 = b * ROWS;
    const int rA = r0 + 2 * wid;               // my warp's two rows
    const int rB = rA + 1;

    // E -> registers: rows rA,rB, cols {ln*4 + k*128 .. +3}, packed f32x2
    ull eA[32], eB[32];
    #pragma unroll
    for (int k = 0; k < 16; k++) {
        const float4 a = *(const float4*)(g_Ef + (size_t)rA * T + ln * 4 + k * 128);
        const float4 c = *(const float4*)(g_Ef + (size_t)rB * T + ln * 4 + k * 128);
        eA[2 * k] = pack2f(a.x, a.y); eA[2 * k + 1] = pack2f(a.z, a.w);
        eB[2 * k] = pack2f(c.x, c.y); eB[2 * k + 1] = pack2f(c.z, c.w);
    }

    double L = 0.0;
    float lr = 0.0f, rinv = 1.0f;   // lagged normalizer state (identical all CTAs)

    for (int t = 0; t < S; t++) {
        // emissions for my rows (off-path, overlaps the poll)
        float eemA = 1.0f, eemB = 1.0f;
        if (ln == 0) {
            float2 em = *(const float2*)(h + (size_t)t * T + rA);
            eemA = __expf(em.x);
            eemB = __expf(em.y);
        }

        // ---- wait for all producers of step t (tid 0, rotating poll) ----
        if (tid == 0) {
            L += (double)lr;
            if (t > 0) {
                const unsigned target = (unsigned)NBLK * (unsigned)t;
                unsigned a0 = poll_once();
                unsigned a1 = poll_once();
                for (;;) {
                    unsigned a2 = poll_once();
                    if (a0 >= target) break;
                    unsigned dly = a2;          // ~130cy delay, opaque to nvcc
                    #pragma unroll
                    for (int d = 0; d < 32; d++)
                        asm volatile("add.u32 %0,%0,1;" : "+r"(dly));
                    asm volatile("" :: "r"(dly));
                    a0 = a1; a1 = a2;
                }
                asm volatile("fence.acq_rel.gpu;" ::: "memory");
            }
        }
        __syncthreads();

        // ---- stage W (f32) into smem: 32B per thread ----
        const float4* gw = (const float4*)(g_Wf[t & 1]);
        float4 w0 = __ldcv(gw + 2 * tid);
        float4 w1 = __ldcv(gw + 2 * tid + 1);
        ((float4*)sW)[2 * tid] = w0;
        ((float4*)sW)[2 * tid + 1] = w1;
        __syncthreads();

        // ---- dot: 2 rows x 64 cols per thread, E in regs, W from smem ----
        ull aA0 = 0ULL, aA1 = 0ULL, aB0 = 0ULL, aB1 = 0ULL;
        #pragma unroll
        for (int k = 0; k < 16; k++) {
            float4 w = ((const float4*)sW)[ln + 32 * k];   // conflict-free
            ull p0 = pack2f(w.x, w.y);
            ull p1 = pack2f(w.z, w.w);
            FMA2(aA0, eA[2 * k], p0); FMA2(aA1, eA[2 * k + 1], p1);
            FMA2(aB0, eB[2 * k], p0); FMA2(aB1, eB[2 * k + 1], p1);
        }
        float x0, x1, y0, y1;
        unpack2f(aA0, x0, x1); unpack2f(aA1, y0, y1);
        float sA = (x0 + x1) + (y0 + y1);
        unpack2f(aB0, x0, x1); unpack2f(aB1, y0, y1);
        float sB = (x0 + x1) + (y0 + y1);
        #pragma unroll
        for (int off = 16; off; off >>= 1) {
            sA += __shfl_xor_sync(0xffffffffu, sA, off);
            sB += __shfl_xor_sync(0xffffffffu, sB, off);
        }
        if (ln == 0) {
            sOut[2 * wid]     = sA * rinv * eemA;
            sOut[2 * wid + 1] = sB * rinv * eemB;
        }
        __syncthreads();

        // ---- publish: 64B + release red (tid 0) ----
        if (tid == 0) {
            float4* dst = (float4*)(g_Wf[(t + 1) & 1] + b * ROWS);
            const float4* so = (const float4*)sOut;
            __stcg(dst + 0, so[0]);
            __stcg(dst + 1, so[1]);
            __stcg(dst + 2, so[2]);
            __stcg(dst + 3, so[3]);
            asm volatile("red.release.gpu.global.add.u32 [%0], %1;"
                         :: "l"(&g_cnt), "r"(1u) : "memory");
        }

        // ---- OFF critical path: next-step normalizer from this step's W ----
        // (sW still valid: overwritten only after next iteration's barrier)
        float mx = 0.0f;
        #pragma unroll
        for (int k = 0; k < 16; k++) {
            float4 w = ((const float4*)sW)[ln + 32 * k];
            mx = fmaxf(mx, fmaxf(fmaxf(w.x, w.y), fmaxf(w.z, w.w)));
        }
        #pragma unroll
        for (int off = 16; off; off >>= 1)
            mx = fmaxf(mx, __shfl_xor_sync(0xffffffffu, mx, off));
        lr = 0.5f * __logf(mx);     // bit-identical in every CTA
        rinv = __expf(-lr);
    }

    // ---- terminal: logZ = log(sum_j W_S[j]*exp(tr[END,j])) + L ----
    if (b == 0) {
        if (tid == 0) {
            const unsigned target = (unsigned)NBLK * (unsigned)S;
            unsigned c;
            do { c = poll_once(); } while (c < target);
            asm volatile("fence.acq_rel.gpu;" ::: "memory");
        }
        __syncthreads();
        const float4* gw = (const float4*)(g_Wf[S & 1]);
        float4 w0 = __ldcv(gw + 2 * tid);
        float4 w1 = __ldcv(gw + 2 * tid + 1);
        const float* te = trans + (size_t)END_IDX * T + tid * 8;
        float p = w0.x * __expf(te[0]) + w0.y * __expf(te[1]) +
                  w0.z * __expf(te[2]) + w0.w * __expf(te[3]) +
                  w1.x * __expf(te[4]) + w1.y * __expf(te[5]) +
                  w1.z * __expf(te[6]) + w1.w * __expf(te[7]);
        __syncthreads();           // sW reads above done; safe to reuse
        sW[tid] = p;
        __syncthreads();
        if (tid == 0) {
            float tot = 0.0f;
            for (int k = 0; k < NTHR; k++) tot += sW[k];
            out[0] = __logf(tot) + (float)L;
        }
    }
}

extern "C" void kernel_launch(void* const* d_in, const int* in_sizes, int n_in,
                              void* d_out, int out_size) {
    const float* h = (const float*)d_in[0];
    const float* trans = (const float*)d_in[1];
    float* out = (float*)d_out;
    int S = in_sizes[0] / T;

    crf_init<<<512, 256>>>(trans);
    crf_main<<<NBLK, NTHR>>>(h, trans, out, S);
}

// round 9
// speedup vs baseline: 1.3446x; 1.3446x over previous
#include <cuda_runtime.h>
#include <cuda_bf16.h>
#include <cstdint>

// CRF forward scan, exp domain. 128 persistent CTAs.
// Fast path: consumers poll their OWN 16B of the bf16 W slot ring with ld.cv
// until no 16-bit half has the sign bit set (canary 0xFFC0). Detect == data
// load: ONE L2 round trip, no pre-dot barrier.
// Liveness guarantee (R9): producers also bump a release counter (post
// __syncwarp, so all 16 data stores are ordered before it). Consumers give up
// the canary poll after 64 tries and fall back to acquire-polling the counter,
// then reload the data once, unconditionally. Every loop terminates.
// Normalizer: lagged sqrt-damped max by warp 1, fully off the critical path.

#define T 2048
#define ROWS 16
#define NBLK 128
#define NTHR 256
#define DEPTH 8
#define START_IDX 0
#define END_IDX 1
#define CANARY 0xFFC0FFC0u
#define POLL_TRIES 64

__device__ __align__(16) float g_Ef[(size_t)T * T];        // 16 MB exp(transitions)
__device__ __align__(16) unsigned g_W[DEPTH][T / 2];        // bf16-pair slot ring
__device__ unsigned g_cnt;                                  // fallback counter

typedef unsigned long long ull;

__device__ __forceinline__ ull pack2f(float a, float b) {
    ull r; asm("mov.b64 %0, {%1, %2};" : "=l"(r) : "f"(a), "f"(b)); return r;
}
__device__ __forceinline__ ull pack2u(unsigned a, unsigned b) {
    ull r; asm("mov.b64 %0, {%1, %2};" : "=l"(r) : "r"(a), "r"(b)); return r;
}
__device__ __forceinline__ void unpack2f(ull p, float& a, float& b) {
    asm("mov.b64 {%0, %1}, %2;" : "=f"(a), "=f"(b) : "l"(p));
}
#define FMA2(acc, a, b) \
    asm("fma.rn.f32x2 %0, %1, %2, %0;" : "+l"(acc) : "l"(a), "l"(b))

__device__ __forceinline__ uint4 ld16cv(const unsigned* p) {
    uint4 w;
    asm volatile("ld.global.cv.v4.u32 {%0,%1,%2,%3}, [%4];"
                 : "=r"(w.x), "=r"(w.y), "=r"(w.z), "=r"(w.w) : "l"(p));
    return w;
}

// Canary poll with bounded tries + counter fallback. Always terminates.
__device__ __forceinline__ uint4 wait16B(const unsigned* p, unsigned cnt_target) {
    uint4 w;
    #pragma unroll 1
    for (int i = 0; i < POLL_TRIES; i++) {
        w = ld16cv(p);
        if (!((w.x | w.y | w.z | w.w) & 0x80008000u)) return w;
        __nanosleep(32);
    }
    // Fallback: counter proves all producer stores are gpu-visible.
    unsigned c;
    do {
        asm volatile("ld.acquire.gpu.global.u32 %0, [%1];" : "=r"(c) : "l"(&g_cnt));
        if (c < cnt_target) __nanosleep(64);
    } while (c < cnt_target);
    return ld16cv(p);
}

__global__ void crf_init(const float* __restrict__ trans) {
    size_t idx = (size_t)blockIdx.x * blockDim.x + threadIdx.x;
    size_t stride = (size_t)gridDim.x * blockDim.x;
    for (size_t i = idx; i < (size_t)T * T; i += stride)
        g_Ef[i] = __expf(trans[i]);
    if (idx < T / 2) {
        g_W[0][idx] = (idx == 0) ? 0x00003F80u : 0u;   // W_0: bf16(1.0) at tag 0
        #pragma unroll
        for (int s = 1; s < DEPTH; s++) g_W[s][idx] = CANARY;
    }
    if (idx == 0) g_cnt = 0u;
}

__global__ void __launch_bounds__(NTHR, 1)
crf_main(const float* __restrict__ h, const float* __restrict__ trans,
         float* __restrict__ out, int S) {
    __shared__ __align__(16) float part[ROWS * NTHR];   // 16KB
    __shared__ __align__(16) float tmp2[ROWS * 16];
    __shared__ __align__(16) float mxs[2][NTHR];        // parity double-buffer
    __shared__ float sNorm[2];
    __shared__ double sL;

    const int tid = threadIdx.x;
    const int wid = tid >> 5;
    const int ln = tid & 31;
    const int b = blockIdx.x;
    const int r0 = b * ROWS;
    const int c0 = wid * 256 + ln * 8;    // my 8 columns
    const int wslot = c0 >> 1;            // word offset of my 16B in a slot

    if (tid == 0) { sNorm[0] = 1.0f; sNorm[1] = 1.0f; }

    // E -> registers: rows r0..r0+15 x my 8 cols, packed f32x2
    ull e64[ROWS][4];
    #pragma unroll
    for (int r = 0; r < ROWS; r++) {
        const float4* ep = (const float4*)(g_Ef + (size_t)(r0 + r) * T + c0);
        float4 a = ep[0], bb = ep[1];
        e64[r][0] = pack2f(a.x, a.y);
        e64[r][1] = pack2f(a.z, a.w);
        e64[r][2] = pack2f(bb.x, bb.y);
        e64[r][3] = pack2f(bb.z, bb.w);
    }

    double L = 0.0;   // meaningful only in tid 32

    for (int t = 0; t < S; t++) {
        // emissions (exp'd) for my row — off-path
        float eem = 1.0f;
        if (tid < ROWS) eem = __expf(__ldg(&h[(size_t)t * T + r0 + tid]));

        // ---- wait for my own 16B of W_t (canary fast path, safe fallback) ----
        uint4 wv = wait16B(g_W[t & 7] + wslot, (unsigned)NBLK * (unsigned)t);

        ull w64[4];
        w64[0] = pack2u(wv.x << 16, wv.x & 0xffff0000u);
        w64[1] = pack2u(wv.y << 16, wv.y & 0xffff0000u);
        w64[2] = pack2u(wv.z << 16, wv.z & 0xffff0000u);
        w64[3] = pack2u(wv.w << 16, wv.w & 0xffff0000u);
        {   // thread-local max for the off-path normalizer — parity buffer
            float m0 = fmaxf(__uint_as_float(wv.x << 16), __uint_as_float(wv.x & 0xffff0000u));
            float m1 = fmaxf(__uint_as_float(wv.y << 16), __uint_as_float(wv.y & 0xffff0000u));
            float m2 = fmaxf(__uint_as_float(wv.z << 16), __uint_as_float(wv.z & 0xffff0000u));
            float m3 = fmaxf(__uint_as_float(wv.w << 16), __uint_as_float(wv.w & 0xffff0000u));
            mxs[t & 1][tid] = fmaxf(fmaxf(m0, m1), fmaxf(m2, m3));
        }

        // ---- dot: 16 rows x 8 cols, E in regs ----
        #pragma unroll
        for (int r = 0; r < ROWS; r++) {
            ull acc = 0ULL;
            FMA2(acc, e64[r][0], w64[0]);
            FMA2(acc, e64[r][1], w64[1]);
            FMA2(acc, e64[r][2], w64[2]);
            FMA2(acc, e64[r][3], w64[3]);
            float x, y;
            unpack2f(acc, x, y);
            part[r * NTHR + tid] = x + y;
        }
        __syncthreads();   // #1

        // ---- stage1: 256 partials/row -> 16/row ----
        {
            int rj = tid >> 4, cj = tid & 15;
            const float4* p4 = (const float4*)(part + rj * NTHR + cj * 16);
            float4 a = p4[0], b4 = p4[1], c4 = p4[2], d4 = p4[3];
            tmp2[rj * 16 + cj] =
                ((a.x + a.y) + (a.z + a.w)) + ((b4.x + b4.y) + (b4.z + b4.w)) +
                ((c4.x + c4.y) + (c4.z + c4.w)) + ((d4.x + d4.y) + (d4.z + d4.w));
        }
        __syncthreads();   // #2

        if (wid == 0) {
            if (ln < ROWS) {
                // ---- stage2: finish my row, scale, publish ----
                const float4* q4 = (const float4*)(tmp2 + ln * 16);
                float4 a = q4[0], b4 = q4[1], c4 = q4[2], d4 = q4[3];
                float rs =
                    ((a.x + a.y) + (a.z + a.w)) + ((b4.x + b4.y) + (b4.z + b4.w)) +
                    ((c4.x + c4.y) + (c4.z + c4.w)) + ((d4.x + d4.y) + (d4.z + d4.w));
                float n = rs * sNorm[t & 1] * eem;
                unsigned short us = __bfloat16_as_ushort(__float2bfloat16(n));
                unsigned short* dst = (unsigned short*)g_W[(t + 1) & 7] + (r0 + ln);
                asm volatile("st.global.cg.u16 [%0], %1;" :: "l"(dst), "h"(us) : "memory");
            }
            __syncwarp();   // memory-sync warp 0: data stores before the red
            if (ln == 16) {
                // release counter: proves W_{t+1} visible (fallback path)
                asm volatile("red.release.gpu.global.add.u32 [%0], %1;"
                             :: "l"(&g_cnt), "r"(1u) : "memory");
            } else if (ln == 17) {
                // clear my CTA's 32B in the slot holding W_{t-2}
                unsigned* cz = g_W[(t + 6) & 7] + (r0 >> 1);
                uint4 cv = make_uint4(CANARY, CANARY, CANARY, CANARY);
                asm volatile("st.global.cg.v4.u32 [%0], {%1,%2,%3,%4};"
                             :: "l"(cz), "r"(cv.x), "r"(cv.y), "r"(cv.z), "r"(cv.w) : "memory");
                asm volatile("st.global.cg.v4.u32 [%0], {%1,%2,%3,%4};"
                             :: "l"(cz + 4), "r"(cv.x), "r"(cv.y), "r"(cv.z), "r"(cv.w) : "memory");
            }
        } else if (wid == 1) {
            // ---- warp 1: lagged damped normalizer for step t+1 (off-path) ----
            const float4* m4 = (const float4*)(mxs[t & 1] + ln * 8);
            float4 a = m4[0], b4 = m4[1];
            float m = fmaxf(fmaxf(fmaxf(a.x, a.y), fmaxf(a.z, a.w)),
                            fmaxf(fmaxf(b4.x, b4.y), fmaxf(b4.z, b4.w)));
            #pragma unroll
            for (int off = 16; off; off >>= 1)
                m = fmaxf(m, __shfl_xor_sync(0xffffffffu, m, off));
            if (ln == 0 && t < S - 1) {
                float lr = 0.5f * __logf(m);        // bit-identical in every CTA
                sNorm[(t + 1) & 1] = __expf(-lr);
                L += (double)lr;                    // tid 32
            }
        }
        // no loop-end sync: free-running warps write only part[] (readers all
        // pre-sync#2) and mxs[(t+1)&1] (warp 1 reads mxs[t&1]) before sync#1
        // of t+1, which warps 0/1 join only after their epilogue. Race-free.
    }

    if (tid == 32) sL = L;

    // ---- terminal: logZ = log(sum_j W_S[j]*exp(tr[END,j])) + L ----
    if (b == 0) {
        uint4 wv = wait16B(g_W[S & 7] + wslot, (unsigned)NBLK * (unsigned)S);
        const float* te = trans + (size_t)END_IDX * T + c0;
        float p =
            __uint_as_float(wv.x << 16)        * __expf(te[0]) +
            __uint_as_float(wv.x & 0xffff0000u)* __expf(te[1]) +
            __uint_as_float(wv.y << 16)        * __expf(te[2]) +
            __uint_as_float(wv.y & 0xffff0000u)* __expf(te[3]) +
            __uint_as_float(wv.z << 16)        * __expf(te[4]) +
            __uint_as_float(wv.z & 0xffff0000u)* __expf(te[5]) +
            __uint_as_float(wv.w << 16)        * __expf(te[6]) +
            __uint_as_float(wv.w & 0xffff0000u)* __expf(te[7]);
        #pragma unroll
        for (int off = 16; off; off >>= 1)
            p += __shfl_xor_sync(0xffffffffu, p, off);
        __syncthreads();
        if (ln == 0) part[wid] = p;
        __syncthreads();
        if (tid == 0) {
            float tot = 0.0f;
            #pragma unroll
            for (int k = 0; k < 8; k++) tot += part[k];
            out[0] = __logf(tot) + (float)sL;
        }
    }
}

extern "C" void kernel_launch(void* const* d_in, const int* in_sizes, int n_in,
                              void* d_out, int out_size) {
    const float* h = (const float*)d_in[0];
    const float* trans = (const float*)d_in[1];
    float* out = (float*)d_out;
    int S = in_sizes[0] / T;

    crf_init<<<512, 256>>>(trans);
    crf_main<<<NBLK, NTHR>>>(h, trans, out, S);
}